// round 13
// baseline (speedup 1.0000x reference)
#include <cuda_runtime.h>
#include <math.h>

#define E_   3072
#define D_   128
#define H_   8
#define HD_  16
#define R_   64
#define FF_  512
#define L_   3
#define CAP_ 128

// ---------------- scratch (no allocations allowed) ----------------
#define OFF_H    0
#define OFF_Q    393216          // q,k,v contiguous -> batched GEMM dst
#define OFF_ATT  1572864
#define OFF_MID  2359296
#define OFF_RBF  3932160
#define OFF_PX   4128768
#define OFF_X    4137984
#define OFF_META 4147200
#define OFF_RBFW 4159488
#define OFF_PART 4945920         // FF2 split-K partials: 2 x E x 128
#define TOTAL_F  5732352

__device__ __align__(16) float g_buf[TOTAL_F];
__device__ int g_ilist[E_ * CAP_];
__device__ int g_xlist[E_ * CAP_];
__device__ int g_icnt[E_];
__device__ int g_xcnt[E_];

// ---------------- packed f32x2 helpers (Blackwell FFMA2) ----------------
typedef unsigned long long ull;
__device__ __forceinline__ ull pack2(float lo, float hi) {
    ull r; asm("mov.b64 %0, {%1, %2};" : "=l"(r) : "f"(lo), "f"(hi)); return r;
}
__device__ __forceinline__ ull dup2(float v) {
    ull r; asm("mov.b64 %0, {%1, %1};" : "=l"(r) : "f"(v)); return r;
}
__device__ __forceinline__ ull fma2(ull a, ull b, ull c) {
    ull d; asm("fma.rn.f32x2 %0, %1, %2, %3;" : "=l"(d) : "l"(a), "l"(b), "l"(c)); return d;
}
__device__ __forceinline__ float2 unpk(ull v) {
    float lo, hi; asm("mov.b64 {%0, %1}, %2;" : "=f"(lo), "=f"(hi) : "l"(v));
    return make_float2(lo, hi);
}

// ---------------- prep: edge meta + rbf + zero px + copy x ----------------
__global__ void prep_kernel(const int* __restrict__ ei, const int* __restrict__ bid,
                            const float* __restrict__ nc, const float* __restrict__ ec,
                            int4* __restrict__ meta, float* __restrict__ rbf,
                            float* __restrict__ px, float* __restrict__ xb) {
    int e = blockIdx.x * 128 + threadIdx.x;
    if (e >= E_) return;
    int s = ei[e], d = ei[E_ + e];
    meta[e] = make_int4(s, d, bid[s], bid[d]);
    px[e*3+0] = 0.f; px[e*3+1] = 0.f; px[e*3+2] = 0.f;
    xb[e*3+0] = ec[e*3+0]; xb[e*3+1] = ec[e*3+1]; xb[e*3+2] = ec[e*3+2];
    float dx = nc[d*3+0] - nc[s*3+0];
    float dy = nc[d*3+1] - nc[s*3+1];
    float dz = nc[d*3+2] - nc[s*3+2];
    float dist = sqrtf(dx*dx + dy*dy + dz*dz);
    float t = fminf(dist * 0.1f, 1.0f);
    float fc = 0.5f * (cosf(3.14159265358979323846f * t) + 1.0f);
    const float inw = 64.0f / 10.0f;   // 1/width, width = CUTOFF/R
    #pragma unroll 8
    for (int r = 0; r < R_; r++) {
        float c = 10.0f * (float)r / 63.0f;   // linspace(0,10,64)
        float u = (dist - c) * inw;
        rbf[e * R_ + r] = expf(-u * u) * fc;
    }
}

// ---------------- build neighbor lists (once; layer/head-invariant) ----------
__global__ void __launch_bounds__(128) build_kernel(const int4* __restrict__ meta) {
    __shared__ int ci, cx;
    int i = blockIdx.x, tid = threadIdx.x;
    if (tid == 0) { ci = 0; cx = 0; }
    __syncthreads();
    int4 mi = meta[i];
    for (int j = tid; j < E_; j += 128) {
        int4 mj = meta[j];
        bool ip = (mi.z == mj.z) && (mi.w == mj.w);
        bool share = (mi.x == mj.x) || (mi.x == mj.y) || (mi.y == mj.x) || (mi.y == mj.y);
        if (ip || (i == j)) {
            int p = atomicAdd(&ci, 1);
            if (p < CAP_) g_ilist[i * CAP_ + p] = j;
        }
        if ((share && !ip) || (i == j)) {
            int p = atomicAdd(&cx, 1);
            if (p < CAP_) g_xlist[i * CAP_ + p] = j;
        }
    }
    __syncthreads();
    if (tid == 0) {
        g_icnt[i] = min(ci, CAP_);
        g_xcnt[i] = min(cx, CAP_);
    }
}

// == fused GEMM: tile 32x128, BK=32, 128 threads, warp owns 8 rows, f32x2 FMA ==
// A rows use leading dim lda; per-z A column offset azk (for split-K).
// EPI 0: C = A@B; z selects B0/B1/B2, C = C0 + z*M*128   (QKV / FF2 split-K parts)
// EPI 5: z selects B; C = A@B (+res if z==0); z=0 -> C0, z>0 -> C12+(z-1)*M*128
// EPI 2: C = silu(A@B + bias)                            (FFN up)
// EPI 3: C = LN(res + A@B)*g + b                         (attn o-proj)
template<int EPI>
__global__ void __launch_bounds__(128) gemm_kernel(
    const float* __restrict__ A, const float* __restrict__ B0,
    const float* __restrict__ B1, const float* __restrict__ B2,
    float* C0, float* C12, const float* res,
    int M, int K, int lda, int azk, int Ntot,
    const float* __restrict__ bias,
    const float* __restrict__ lng, const float* __restrict__ lnb)
{
    __shared__ __align__(16) float As[2][32 * 34];   // k-major, stride 34
    __shared__ __align__(16) float Bs[2][32][128];
    int z = blockIdx.z;
    const float* B = (z == 0) ? B0 : ((z == 1) ? B1 : B2);
    const float* Ab = A + (size_t)z * azk;
    float* C;
    if (EPI == 0)      C = C0 + (size_t)z * M * 128;
    else if (EPI == 5) C = (z == 0) ? C0 : (C12 + (size_t)(z - 1) * M * 128);
    else               C = C0;

    int tid = threadIdx.x, tx = tid & 31, w = tid >> 5;   // 4 warps
    int m0 = blockIdx.y << 5, cb = blockIdx.x << 7;
    int nt = K >> 5;
    int am = tid >> 2, ak = (tid & 3) << 3;          // A: row am, k cols ak..ak+7
    int brb = tid >> 5, bc4 = (tid & 31) << 2;       // B: rows brb+4j, j=0..7

    // prologue: tile 0 -> smem[0]
    float4 pa0 = *(const float4*)&Ab[(size_t)(m0 + am) * lda + ak];
    float4 pa1 = *(const float4*)&Ab[(size_t)(m0 + am) * lda + ak + 4];
    float4 pb[8];
    #pragma unroll
    for (int j = 0; j < 8; j++)
        pb[j] = *(const float4*)&B[(size_t)(brb + 4 * j) * Ntot + cb + bc4];
    As[0][(ak + 0) * 34 + am] = pa0.x;
    As[0][(ak + 1) * 34 + am] = pa0.y;
    As[0][(ak + 2) * 34 + am] = pa0.z;
    As[0][(ak + 3) * 34 + am] = pa0.w;
    As[0][(ak + 4) * 34 + am] = pa1.x;
    As[0][(ak + 5) * 34 + am] = pa1.y;
    As[0][(ak + 6) * 34 + am] = pa1.z;
    As[0][(ak + 7) * 34 + am] = pa1.w;
    #pragma unroll
    for (int j = 0; j < 8; j++)
        *(float4*)&Bs[0][brb + 4 * j][bc4] = pb[j];
    __syncthreads();

    ull c2[4][4];
    #pragma unroll
    for (int p = 0; p < 4; p++)
        #pragma unroll
        for (int c = 0; c < 4; c++) c2[p][c] = 0ULL;

    for (int t = 0; t < nt; t++) {
        int cur = t & 1;
        if (t + 1 < nt) {               // register prefetch overlaps compute
            int k0 = (t + 1) << 5;
            pa0 = *(const float4*)&Ab[(size_t)(m0 + am) * lda + k0 + ak];
            pa1 = *(const float4*)&Ab[(size_t)(m0 + am) * lda + k0 + ak + 4];
            #pragma unroll
            for (int j = 0; j < 8; j++)
                pb[j] = *(const float4*)&B[(size_t)(k0 + brb + 4 * j) * Ntot + cb + bc4];
        }
        #pragma unroll
        for (int k = 0; k < 32; k++) {
            const float* Ac = &As[cur][k * 34 + (w << 3)];
            float2 a01 = *(const float2*)&Ac[0];
            float2 a23 = *(const float2*)&Ac[2];
            float2 a45 = *(const float2*)&Ac[4];
            float2 a67 = *(const float2*)&Ac[6];
            float4 bv  = *(const float4*)&Bs[cur][k][tx << 2];
            ull A01 = pack2(a01.x, a01.y);
            ull A23 = pack2(a23.x, a23.y);
            ull A45 = pack2(a45.x, a45.y);
            ull A67 = pack2(a67.x, a67.y);
            ull D0 = dup2(bv.x), D1 = dup2(bv.y), D2 = dup2(bv.z), D3 = dup2(bv.w);
            c2[0][0] = fma2(A01, D0, c2[0][0]);  c2[1][0] = fma2(A23, D0, c2[1][0]);
            c2[2][0] = fma2(A45, D0, c2[2][0]);  c2[3][0] = fma2(A67, D0, c2[3][0]);
            c2[0][1] = fma2(A01, D1, c2[0][1]);  c2[1][1] = fma2(A23, D1, c2[1][1]);
            c2[2][1] = fma2(A45, D1, c2[2][1]);  c2[3][1] = fma2(A67, D1, c2[3][1]);
            c2[0][2] = fma2(A01, D2, c2[0][2]);  c2[1][2] = fma2(A23, D2, c2[1][2]);
            c2[2][2] = fma2(A45, D2, c2[2][2]);  c2[3][2] = fma2(A67, D2, c2[3][2]);
            c2[0][3] = fma2(A01, D3, c2[0][3]);  c2[1][3] = fma2(A23, D3, c2[1][3]);
            c2[2][3] = fma2(A45, D3, c2[2][3]);  c2[3][3] = fma2(A67, D3, c2[3][3]);
        }
        if (t + 1 < nt) {
            int nb = cur ^ 1;
            As[nb][(ak + 0) * 34 + am] = pa0.x;
            As[nb][(ak + 1) * 34 + am] = pa0.y;
            As[nb][(ak + 2) * 34 + am] = pa0.z;
            As[nb][(ak + 3) * 34 + am] = pa0.w;
            As[nb][(ak + 4) * 34 + am] = pa1.x;
            As[nb][(ak + 5) * 34 + am] = pa1.y;
            As[nb][(ak + 6) * 34 + am] = pa1.z;
            As[nb][(ak + 7) * 34 + am] = pa1.w;
            #pragma unroll
            for (int j = 0; j < 8; j++)
                *(float4*)&Bs[nb][brb + 4 * j][bc4] = pb[j];
        }
        __syncthreads();
    }

    // unpack: val[i][c], rows r0+i (i=0..7), cols cg+c
    float val[8][4];
    #pragma unroll
    for (int p = 0; p < 4; p++)
        #pragma unroll
        for (int c = 0; c < 4; c++) {
            float2 u = unpk(c2[p][c]);
            val[2*p + 0][c] = u.x;
            val[2*p + 1][c] = u.y;
        }
    int cg = cb + (tx << 2);
    int r0 = m0 + (w << 3);

    if (EPI == 0 || EPI == 5) {
        #pragma unroll
        for (int i = 0; i < 8; i++) {
            float4 o = make_float4(val[i][0], val[i][1], val[i][2], val[i][3]);
            if (EPI == 5 && z == 0) {
                float4 rv = *(const float4*)&res[(size_t)(r0 + i) * Ntot + cg];
                o.x += rv.x; o.y += rv.y; o.z += rv.z; o.w += rv.w;
            }
            *(float4*)&C[(size_t)(r0 + i) * Ntot + cg] = o;
        }
        return;
    }
    if (EPI == 2) {
        float4 bv = *(const float4*)&bias[cg];
        #pragma unroll
        for (int i = 0; i < 8; i++) {
            float v0 = val[i][0] + bv.x, v1 = val[i][1] + bv.y;
            float v2 = val[i][2] + bv.z, v3 = val[i][3] + bv.w;
            v0 = v0 / (1.0f + __expf(-v0));
            v1 = v1 / (1.0f + __expf(-v1));
            v2 = v2 / (1.0f + __expf(-v2));
            v3 = v3 / (1.0f + __expf(-v3));
            *(float4*)&C[(size_t)(r0 + i) * Ntot + cg] = make_float4(v0, v1, v2, v3);
        }
        return;
    }

    // EPI 3: residual, row LayerNorm (warp owns full rows)
    #pragma unroll
    for (int i = 0; i < 8; i++) {
        float4 rv = *(const float4*)&res[(size_t)(r0 + i) * 128 + cg];
        val[i][0] += rv.x;  val[i][1] += rv.y;
        val[i][2] += rv.z;  val[i][3] += rv.w;
    }
    float s[8], sq[8];
    #pragma unroll
    for (int i = 0; i < 8; i++) {
        s[i]  = val[i][0] + val[i][1] + val[i][2] + val[i][3];
        sq[i] = val[i][0]*val[i][0] + val[i][1]*val[i][1]
              + val[i][2]*val[i][2] + val[i][3]*val[i][3];
    }
    #pragma unroll
    for (int o = 16; o > 0; o >>= 1) {
        #pragma unroll
        for (int i = 0; i < 8; i++) {
            s[i]  += __shfl_xor_sync(0xffffffffu, s[i],  o);
            sq[i] += __shfl_xor_sync(0xffffffffu, sq[i], o);
        }
    }
    float4 g4 = *(const float4*)&lng[cg];
    float4 b4 = *(const float4*)&lnb[cg];
    #pragma unroll
    for (int i = 0; i < 8; i++) {
        float mean = s[i] * (1.0f / 128.0f);
        float var  = fmaxf(sq[i] * (1.0f / 128.0f) - mean * mean, 0.0f);
        float rstd = rsqrtf(var + 1e-5f);
        float h0 = (val[i][0] - mean) * rstd * g4.x + b4.x;
        float h1 = (val[i][1] - mean) * rstd * g4.y + b4.y;
        float h2 = (val[i][2] - mean) * rstd * g4.z + b4.z;
        float h3 = (val[i][3] - mean) * rstd * g4.w + b4.w;
        *(float4*)&C[(size_t)(r0 + i) * 128 + cg] = make_float4(h0, h1, h2, h3);
    }
}

// ---- FF2 epilogue: t = LN(h + part0 + part1 + b2)*g + b; gate = tanh(t@Wc+bc);
//      x += gate*(x-px); px = 0; h = t (+ next layer's rbfW)
__global__ void __launch_bounds__(128) ff2_epi_kernel(
    const float* __restrict__ part, float* __restrict__ h,
    const float* __restrict__ b2,
    const float* __restrict__ g, const float* __restrict__ b,
    const float* __restrict__ Wc, const float* __restrict__ bc,
    float* __restrict__ px, float* __restrict__ x,
    const float* __restrict__ extra)
{
    int row = blockIdx.x, tid = threadIdx.x;
    int idx = row * 128 + tid;
    float t = h[idx] + part[idx] + part[E_ * 128 + idx] + b2[tid];
    float s = t, sq = t * t;
    #pragma unroll
    for (int o = 16; o > 0; o >>= 1) {
        s  += __shfl_xor_sync(0xffffffffu, s,  o);
        sq += __shfl_xor_sync(0xffffffffu, sq, o);
    }
    __shared__ float ss[4], sqs[4], gs[4];
    if ((tid & 31) == 0) { ss[tid >> 5] = s; sqs[tid >> 5] = sq; }
    __syncthreads();
    float S  = ss[0] + ss[1] + ss[2] + ss[3];
    float SQ = sqs[0] + sqs[1] + sqs[2] + sqs[3];
    float mean = S * (1.0f / 128.0f);
    float var = fmaxf(SQ * (1.0f / 128.0f) - mean * mean, 0.0f);
    float rstd = rsqrtf(var + 1e-5f);
    float hn = (t - mean) * rstd * g[tid] + b[tid];
    float gp = hn * Wc[tid];
    #pragma unroll
    for (int o = 16; o > 0; o >>= 1) gp += __shfl_xor_sync(0xffffffffu, gp, o);
    if ((tid & 31) == 0) gs[tid >> 5] = gp;
    __syncthreads();
    h[idx] = hn + (extra ? extra[idx] : 0.0f);
    if (tid < 3) {
        float gd = gs[0] + gs[1] + gs[2] + gs[3];
        float gt = tanhf(gd + bc[0]);
        float xv = x[row * 3 + tid];
        float pv = px[row * 3 + tid];
        x[row * 3 + tid]  = xv + gt * (xv - pv);
        px[row * 3 + tid] = 0.0f;   // ready for next layer / next replay
    }
}

// ---------------- sparse masked attention: one warp per (query, head) -----------
// Lanes split as (half, d): d = lane&15 is the head-dim, half = lane>>4 splits the
// neighbor list. Streaming softmax; halves merged via shfl at the end.
// In-loop shuffles use per-half masks (halves have different trip counts when n odd).
// INTRA also accumulates px[i] = mean_h sum_j p[h,i,j] * x[j] (atomicAdd, 3 lanes).
template<bool INTRA>
__global__ void __launch_bounds__(256) attn_kernel(
    const float* __restrict__ q, const float* __restrict__ k, const float* __restrict__ v,
    const float* __restrict__ x, float* __restrict__ out, float* __restrict__ px)
{
    int warp = threadIdx.x >> 5, lane = threadIdx.x & 31;
    int i = blockIdx.x * 8 + warp;
    int head = blockIdx.y;
    int off = head * HD_;
    int d = lane & 15, half = lane >> 4;
    unsigned hm = half ? 0xffff0000u : 0x0000ffffu;   // lanes of MY half only

    float qd = q[i * D_ + off + d];
    int n = INTRA ? g_icnt[i] : g_xcnt[i];
    const int* li = (INTRA ? g_ilist : g_xlist) + i * CAP_;

    float m = -1e30f, l = 0.0f, acc = 0.0f, ax = 0.0f;

    for (int t = half; t < n; t += 2) {
        int j = li[t];
        float s = qd * k[j * D_ + off + d];
        s += __shfl_xor_sync(hm, s, 8);
        s += __shfl_xor_sync(hm, s, 4);
        s += __shfl_xor_sync(hm, s, 2);
        s += __shfl_xor_sync(hm, s, 1);
        s *= 0.25f;  // 1/sqrt(16)
        float vd = v[j * D_ + off + d];
        float mn = fmaxf(m, s);
        float cc = __expf(m - mn), p = __expf(s - mn);
        l = l * cc + p;
        acc = acc * cc + p * vd;
        if (INTRA && d < 3) ax = ax * cc + p * x[j * 3 + d];
        m = mn;
    }

    // merge the two halves (all 32 lanes re-converged -> full mask legal)
    float m2 = __shfl_xor_sync(0xffffffffu, m, 16);
    float l2 = __shfl_xor_sync(0xffffffffu, l, 16);
    float a2 = __shfl_xor_sync(0xffffffffu, acc, 16);
    float mn = fmaxf(m, m2);
    float c1 = __expf(m - mn), c2 = __expf(m2 - mn);
    l = l * c1 + l2 * c2;
    acc = acc * c1 + a2 * c2;
    if (INTRA) {
        float x2 = __shfl_xor_sync(0xffffffffu, ax, 16);
        ax = ax * c1 + x2 * c2;
    }
    float inv = 1.0f / l;  // diag always present -> l > 0
    if (half == 0) {
        out[i * D_ + off + d] = acc * inv;
        if (INTRA && d < 3) atomicAdd(&px[i * 3 + d], ax * inv * 0.125f);
    }
}

// ---------------- output: concat(h, x) ----------------
__global__ void out_kernel(const float* __restrict__ h, const float* __restrict__ x,
                           float* __restrict__ out, int out_size)
{
    int i = blockIdx.x * 256 + threadIdx.x;
    if (i >= out_size) return;
    if (i < E_ * D_)               out[i] = h[i];
    else if (i < E_ * D_ + E_ * 3) out[i] = x[i - E_ * D_];
    else                           out[i] = 0.0f;
}

// ---------------- host ----------------
extern "C" void kernel_launch(void* const* d_in, const int* in_sizes, int n_in,
                              void* d_out, int out_size)
{
    const float* edge_features = (const float*)d_in[0];
    const float* edge_coords   = (const float*)d_in[1];
    const int*   edge_index    = (const int*)  d_in[2];
    const float* node_coords   = (const float*)d_in[3];
    const int*   block_ids     = (const int*)  d_in[4];
    const float* Wq_a = (const float*)d_in[5];
    const float* Wk_a = (const float*)d_in[6];
    const float* Wv_a = (const float*)d_in[7];
    const float* Wo_a = (const float*)d_in[8];
    const float* Wq_e = (const float*)d_in[9];
    const float* Wk_e = (const float*)d_in[10];
    const float* Wv_e = (const float*)d_in[11];
    const float* Wo_e = (const float*)d_in[12];
    const float* W1   = (const float*)d_in[13];
    const float* b1   = (const float*)d_in[14];
    const float* W2   = (const float*)d_in[15];
    const float* b2   = (const float*)d_in[16];
    const float* ln1g = (const float*)d_in[17];
    const float* ln1b = (const float*)d_in[18];
    const float* ln2g = (const float*)d_in[19];
    const float* ln2b = (const float*)d_in[20];
    const float* ln3g = (const float*)d_in[21];
    const float* ln3b = (const float*)d_in[22];
    const float* Wrbf = (const float*)d_in[23];
    const float* Wc   = (const float*)d_in[24];
    const float* bc   = (const float*)d_in[25];

    float* buf = nullptr;
    cudaGetSymbolAddress((void**)&buf, g_buf);
    float* h    = buf + OFF_H;
    float* qb   = buf + OFF_Q;
    float* kb   = qb + E_ * D_;
    float* vb   = qb + 2 * E_ * D_;
    float* att  = buf + OFF_ATT;
    float* mid  = buf + OFF_MID;
    float* rbf  = buf + OFF_RBF;
    float* px   = buf + OFF_PX;
    float* xb   = buf + OFF_X;
    int4*  meta = (int4*)(buf + OFF_META);
    float* rbfW = buf + OFF_RBFW;   // rbfW for layers 1,2 (layer 0 folds into h)
    float* part = buf + OFF_PART;   // FF2 split-K partials

    dim3 g1(1, E_ / 32, 1);          // 96 blocks
    dim3 g3(1, E_ / 32, 3);          // 288 blocks
    dim3 gF(FF_ / 128, E_ / 32, 1);  // 384 blocks
    dim3 g2(1, E_ / 32, 2);          // 192 blocks (FF2 split-K)
    dim3 gAttn(E_ / 8, H_);          // 384 blocks

    prep_kernel<<<(E_ + 127) / 128, 128>>>(edge_index, block_ids, node_coords,
                                           edge_coords, meta, rbf, px, xb);
    build_kernel<<<E_, 128>>>(meta);

    // rbfW_l = rbf @ Wrbf[l] for all 3 layers in one launch.
    // z=0 -> h = edge_features + rbfW_0 (layer-0 h'); z=1,2 -> rbfW buffers.
    gemm_kernel<5><<<g3, 128>>>(rbf, Wrbf, Wrbf + R_ * D_, Wrbf + 2 * R_ * D_,
                                h, rbfW, edge_features, E_, R_, R_, 0, D_,
                                nullptr, nullptr, nullptr);

    for (int l = 0; l < L_; l++) {
        const int DD = D_ * D_;
        const float* nextRbfW = (l < 2) ? (rbfW + (size_t)l * E_ * D_) : nullptr;

        // --- intra attention ---
        gemm_kernel<0><<<g3, 128>>>(h, Wq_a + l * DD, Wk_a + l * DD, Wv_a + l * DD,
                                    qb, nullptr, nullptr, E_, D_, D_, 0, D_,
                                    nullptr, nullptr, nullptr);
        attn_kernel<true><<<gAttn, 256>>>(qb, kb, vb, xb, att, px);
        gemm_kernel<3><<<g1, 128>>>(att, Wo_a + l * DD, nullptr, nullptr,
                                    h, nullptr, h, E_, D_, D_, 0, D_,
                                    nullptr, ln1g + l * D_, ln1b + l * D_);

        // --- inter attention ---
        gemm_kernel<0><<<g3, 128>>>(h, Wq_e + l * DD, Wk_e + l * DD, Wv_e + l * DD,
                                    qb, nullptr, nullptr, E_, D_, D_, 0, D_,
                                    nullptr, nullptr, nullptr);
        attn_kernel<false><<<gAttn, 256>>>(qb, kb, vb, xb, att, nullptr);
        gemm_kernel<3><<<g1, 128>>>(att, Wo_e + l * DD, nullptr, nullptr,
                                    h, nullptr, h, E_, D_, D_, 0, D_,
                                    nullptr, ln2g + l * D_, ln2b + l * D_);

        // --- FFN: up-proj (silu), then split-K down-proj + fused epilogue ---
        gemm_kernel<2><<<gF, 128>>>(h, W1 + (size_t)l * D_ * FF_, nullptr, nullptr,
                                    mid, nullptr, nullptr, E_, D_, D_, 0, FF_,
                                    b1 + l * FF_, nullptr, nullptr);
        // z in {0,1}: part_z = mid[:, z*256:(z+1)*256] @ W2[z*256:(z+1)*256, :]
        gemm_kernel<0><<<g2, 128>>>(mid, W2 + (size_t)l * FF_ * D_,
                                    W2 + (size_t)l * FF_ * D_ + 256 * D_, nullptr,
                                    part, nullptr, nullptr, E_, 256, FF_, 256, D_,
                                    nullptr, nullptr, nullptr);
        ff2_epi_kernel<<<E_, 128>>>(part, h, b2 + l * D_,
                                    ln3g + l * D_, ln3b + l * D_,
                                    Wc + l * D_, bc + l, px, xb, nextRbfW);
    }

    out_kernel<<<(out_size + 255) / 256, 256>>>(h, xb, (float*)d_out, out_size);
}

// round 15
// speedup vs baseline: 1.1875x; 1.1875x over previous
#include <cuda_runtime.h>
#include <cuda_bf16.h>
#include <math.h>

#define E_   3072
#define D_   128
#define H_   8
#define HD_  16
#define R_   64
#define FF_  512
#define L_   3
#define CAP_ 128

// ---------------- scratch (no allocations allowed) ----------------
#define OFF_H    0
#define OFF_Q    393216          // q,k,v contiguous
#define OFF_ATT  1572864
#define OFF_MID  2359296
#define OFF_RBF  3932160
#define OFF_PX   4128768
#define OFF_X    4137984
#define OFF_META 4147200
#define OFF_RBFW 4159488
#define OFF_PART 4945920         // FF2 split-K partials: 2 x E x 128
#define TOTAL_F  5732352

__device__ __align__(16) float g_buf[TOTAL_F];
__device__ int g_ilist[E_ * CAP_];
__device__ int g_xlist[E_ * CAP_];
__device__ int g_icnt[E_];
__device__ int g_xcnt[E_];

// ---------------- packed f32x2 helpers (Blackwell FFMA2) ----------------
typedef unsigned long long ull;
__device__ __forceinline__ ull pack2(float lo, float hi) {
    ull r; asm("mov.b64 %0, {%1, %2};" : "=l"(r) : "f"(lo), "f"(hi)); return r;
}
__device__ __forceinline__ ull dup2(float v) {
    ull r; asm("mov.b64 %0, {%1, %1};" : "=l"(r) : "f"(v)); return r;
}
__device__ __forceinline__ ull fma2(ull a, ull b, ull c) {
    ull d; asm("fma.rn.f32x2 %0, %1, %2, %3;" : "=l"(d) : "l"(a), "l"(b), "l"(c)); return d;
}
__device__ __forceinline__ float2 unpk(ull v) {
    float lo, hi; asm("mov.b64 {%0, %1}, %2;" : "=f"(lo), "=f"(hi) : "l"(v));
    return make_float2(lo, hi);
}

// ---------------- bf16 split helpers ----------------
// Split two fp32 (consecutive k) into packed bf16x2 hi and lo halves.
__device__ __forceinline__ void split2(float x, float y, unsigned& hi, unsigned& lo) {
    __nv_bfloat16 hx = __float2bfloat16(x), hy = __float2bfloat16(y);
    __nv_bfloat16 lx = __float2bfloat16(x - __bfloat162float(hx));
    __nv_bfloat16 ly = __float2bfloat16(y - __bfloat162float(hy));
    hi = (unsigned)__bfloat16_as_ushort(hx) | ((unsigned)__bfloat16_as_ushort(hy) << 16);
    lo = (unsigned)__bfloat16_as_ushort(lx) | ((unsigned)__bfloat16_as_ushort(ly) << 16);
}

// warp-level MMA m16n8k16 bf16 -> f32 accumulate (sm_80+, valid on sm_100)
__device__ __forceinline__ void mma16816(float* c, unsigned a0, unsigned a1,
                                         unsigned a2, unsigned a3,
                                         unsigned b0, unsigned b1) {
    asm volatile(
        "mma.sync.aligned.m16n8k16.row.col.f32.bf16.bf16.f32 "
        "{%0,%1,%2,%3}, {%4,%5,%6,%7}, {%8,%9}, {%0,%1,%2,%3};"
        : "+f"(c[0]), "+f"(c[1]), "+f"(c[2]), "+f"(c[3])
        : "r"(a0), "r"(a1), "r"(a2), "r"(a3), "r"(b0), "r"(b1));
}

// ---------------- prep: edge meta + rbf + zero px + copy x ----------------
__global__ void prep_kernel(const int* __restrict__ ei, const int* __restrict__ bid,
                            const float* __restrict__ nc, const float* __restrict__ ec,
                            int4* __restrict__ meta, float* __restrict__ rbf,
                            float* __restrict__ px, float* __restrict__ xb) {
    int e = blockIdx.x * 128 + threadIdx.x;
    if (e >= E_) return;
    int s = ei[e], d = ei[E_ + e];
    meta[e] = make_int4(s, d, bid[s], bid[d]);
    px[e*3+0] = 0.f; px[e*3+1] = 0.f; px[e*3+2] = 0.f;
    xb[e*3+0] = ec[e*3+0]; xb[e*3+1] = ec[e*3+1]; xb[e*3+2] = ec[e*3+2];
    float dx = nc[d*3+0] - nc[s*3+0];
    float dy = nc[d*3+1] - nc[s*3+1];
    float dz = nc[d*3+2] - nc[s*3+2];
    float dist = sqrtf(dx*dx + dy*dy + dz*dz);
    float t = fminf(dist * 0.1f, 1.0f);
    float fc = 0.5f * (cosf(3.14159265358979323846f * t) + 1.0f);
    const float inw = 64.0f / 10.0f;   // 1/width, width = CUTOFF/R
    #pragma unroll 8
    for (int r = 0; r < R_; r++) {
        float c = 10.0f * (float)r / 63.0f;   // linspace(0,10,64)
        float u = (dist - c) * inw;
        rbf[e * R_ + r] = expf(-u * u) * fc;
    }
}

// ---------------- build neighbor lists (once; layer/head-invariant) ----------
__global__ void __launch_bounds__(128) build_kernel(const int4* __restrict__ meta) {
    __shared__ int ci, cx;
    int i = blockIdx.x, tid = threadIdx.x;
    if (tid == 0) { ci = 0; cx = 0; }
    __syncthreads();
    int4 mi = meta[i];
    for (int j = tid; j < E_; j += 128) {
        int4 mj = meta[j];
        bool ip = (mi.z == mj.z) && (mi.w == mj.w);
        bool share = (mi.x == mj.x) || (mi.x == mj.y) || (mi.y == mj.x) || (mi.y == mj.y);
        if (ip || (i == j)) {
            int p = atomicAdd(&ci, 1);
            if (p < CAP_) g_ilist[i * CAP_ + p] = j;
        }
        if ((share && !ip) || (i == j)) {
            int p = atomicAdd(&cx, 1);
            if (p < CAP_) g_xlist[i * CAP_ + p] = j;
        }
    }
    __syncthreads();
    if (tid == 0) {
        g_icnt[i] = min(ci, CAP_);
        g_xcnt[i] = min(cx, CAP_);
    }
}

// ====== tensor-core GEMM via mma.sync bf16 split-3: tile 32x128, BK=32 ==========
// fp32 A,B are split on staging into (hi, lo) bf16 pairs (k-pair packed).
// Accumulates hiA*hiB + hiA*loB + loA*hiB in f32 (drops loA*loB, ~1e-5 rel).
// 256 threads = 8 warps laid out 2(m) x 4(n); each warp: 16 rows x 32 cols.
// EPI 0: C = A@B; z selects B0/B1/B2, C = C0 + z*M*128   (QKV / FF2 split-K parts)
// EPI 5: z selects B; C = A@B (+res if z==0); z=0 -> C0, z>0 -> C12+(z-1)*M*128
// EPI 2: C = silu(A@B + bias)                            (FFN up)
template<int EPI>
__global__ void __launch_bounds__(256) mma_gemm(
    const float* __restrict__ A, const float* __restrict__ B0,
    const float* __restrict__ B1, const float* __restrict__ B2,
    float* C0, float* C12, const float* res,
    int M, int K, int lda, int azk, int Ntot,
    const float* __restrict__ bias)
{
    // As: [32 rows][20] packed k-pairs (16 used, stride 20 -> conflict-free frag loads)
    // Bs: [16 k-pairs][136] cols (128 used, stride 136 -> conflict-free frag loads)
    __shared__ __align__(16) unsigned AsHi[2][32 * 20], AsLo[2][32 * 20];
    __shared__ __align__(16) unsigned BsHi[2][16 * 136], BsLo[2][16 * 136];

    int z = blockIdx.z;
    const float* B = (z == 0) ? B0 : ((z == 1) ? B1 : B2);
    const float* Ab = A + (size_t)z * azk;
    float* C;
    if (EPI == 0)      C = C0 + (size_t)z * M * 128;
    else if (EPI == 5) C = (z == 0) ? C0 : (C12 + (size_t)(z - 1) * M * 128);
    else               C = C0;

    int tid = threadIdx.x, lane = tid & 31, wid = tid >> 5;
    int m0 = blockIdx.y << 5, cb = blockIdx.x << 7;
    int nt = K >> 5;

    // staging indices
    int am = tid >> 3, ak4 = (tid & 7) << 2;      // A: one float4 per thread
    int k2i = (tid & 7) << 1;                      // k-pair index of that float4
    // B: 2 units per thread; unit u covers rows 2*bk2, 2*bk2+1, cols bn4..bn4+3

    // frag indices
    int wm = wid >> 2, wn = wid & 3;
    int ar = (wm << 4) + (lane >> 2);              // A row (a0); a1 at +8
    int ac = lane & 3;                              // k-pair within kstep
    int bcc = (wn << 5) + (lane >> 2);             // B col (subtile 0); +8 per subtile
    int bk = lane & 3;

    // ---- prologue: stage tile 0 into buffer 0
    {
        float4 a4 = *(const float4*)&Ab[(size_t)(m0 + am) * lda + ak4];
        unsigned h0, l0, h1, l1;
        split2(a4.x, a4.y, h0, l0);
        split2(a4.z, a4.w, h1, l1);
        AsHi[0][am * 20 + k2i] = h0;  AsHi[0][am * 20 + k2i + 1] = h1;
        AsLo[0][am * 20 + k2i] = l0;  AsLo[0][am * 20 + k2i + 1] = l1;
        #pragma unroll
        for (int j = 0; j < 2; j++) {
            int u = tid + (j << 8);
            int bk2 = u >> 5, bn4 = (u & 31) << 2;
            float4 r0 = *(const float4*)&B[(size_t)(2 * bk2) * Ntot + cb + bn4];
            float4 r1 = *(const float4*)&B[(size_t)(2 * bk2 + 1) * Ntot + cb + bn4];
            unsigned hh, ll;
            split2(r0.x, r1.x, hh, ll); BsHi[0][bk2*136 + bn4+0] = hh; BsLo[0][bk2*136 + bn4+0] = ll;
            split2(r0.y, r1.y, hh, ll); BsHi[0][bk2*136 + bn4+1] = hh; BsLo[0][bk2*136 + bn4+1] = ll;
            split2(r0.z, r1.z, hh, ll); BsHi[0][bk2*136 + bn4+2] = hh; BsLo[0][bk2*136 + bn4+2] = ll;
            split2(r0.w, r1.w, hh, ll); BsHi[0][bk2*136 + bn4+3] = hh; BsLo[0][bk2*136 + bn4+3] = ll;
        }
    }
    __syncthreads();

    float acc[4][4];
    #pragma unroll
    for (int s = 0; s < 4; s++)
        #pragma unroll
        for (int c = 0; c < 4; c++) acc[s][c] = 0.0f;

    for (int t = 0; t < nt; t++) {
        int cur = t & 1;
        float4 apf;
        float4 bpf[4];
        if (t + 1 < nt) {               // register prefetch overlaps compute
            int k0 = (t + 1) << 5;
            apf = *(const float4*)&Ab[(size_t)(m0 + am) * lda + k0 + ak4];
            #pragma unroll
            for (int j = 0; j < 2; j++) {
                int u = tid + (j << 8);
                int bk2 = u >> 5, bn4 = (u & 31) << 2;
                bpf[2*j]   = *(const float4*)&B[(size_t)(k0 + 2 * bk2) * Ntot + cb + bn4];
                bpf[2*j+1] = *(const float4*)&B[(size_t)(k0 + 2 * bk2 + 1) * Ntot + cb + bn4];
            }
        }
        #pragma unroll
        for (int ks = 0; ks < 2; ks++) {
            int k2b = ks << 3;
            unsigned aH0 = AsHi[cur][ ar      * 20 + k2b + ac];
            unsigned aH1 = AsHi[cur][(ar + 8) * 20 + k2b + ac];
            unsigned aH2 = AsHi[cur][ ar      * 20 + k2b + 4 + ac];
            unsigned aH3 = AsHi[cur][(ar + 8) * 20 + k2b + 4 + ac];
            unsigned aL0 = AsLo[cur][ ar      * 20 + k2b + ac];
            unsigned aL1 = AsLo[cur][(ar + 8) * 20 + k2b + ac];
            unsigned aL2 = AsLo[cur][ ar      * 20 + k2b + 4 + ac];
            unsigned aL3 = AsLo[cur][(ar + 8) * 20 + k2b + 4 + ac];
            #pragma unroll
            for (int s = 0; s < 4; s++) {
                int bi0 = (k2b + bk) * 136 + bcc + (s << 3);
                int bi1 = (k2b + 4 + bk) * 136 + bcc + (s << 3);
                unsigned bH0 = BsHi[cur][bi0], bH1 = BsHi[cur][bi1];
                unsigned bL0 = BsLo[cur][bi0], bL1 = BsLo[cur][bi1];
                mma16816(acc[s], aH0, aH1, aH2, aH3, bH0, bH1);
                mma16816(acc[s], aH0, aH1, aH2, aH3, bL0, bL1);
                mma16816(acc[s], aL0, aL1, aL2, aL3, bH0, bH1);
            }
        }
        if (t + 1 < nt) {
            int nb = cur ^ 1;
            unsigned h0, l0, h1, l1;
            split2(apf.x, apf.y, h0, l0);
            split2(apf.z, apf.w, h1, l1);
            AsHi[nb][am * 20 + k2i] = h0;  AsHi[nb][am * 20 + k2i + 1] = h1;
            AsLo[nb][am * 20 + k2i] = l0;  AsLo[nb][am * 20 + k2i + 1] = l1;
            #pragma unroll
            for (int j = 0; j < 2; j++) {
                int u = tid + (j << 8);
                int bk2 = u >> 5, bn4 = (u & 31) << 2;
                float4 r0 = bpf[2*j], r1 = bpf[2*j+1];
                unsigned hh, ll;
                split2(r0.x, r1.x, hh, ll); BsHi[nb][bk2*136 + bn4+0] = hh; BsLo[nb][bk2*136 + bn4+0] = ll;
                split2(r0.y, r1.y, hh, ll); BsHi[nb][bk2*136 + bn4+1] = hh; BsLo[nb][bk2*136 + bn4+1] = ll;
                split2(r0.z, r1.z, hh, ll); BsHi[nb][bk2*136 + bn4+2] = hh; BsLo[nb][bk2*136 + bn4+2] = ll;
                split2(r0.w, r1.w, hh, ll); BsHi[nb][bk2*136 + bn4+3] = hh; BsLo[nb][bk2*136 + bn4+3] = ll;
            }
        }
        __syncthreads();
    }

    // ---- epilogue: lane holds rows r0, r0+8; cols c0+s*8, c0+s*8+1
    int r0 = m0 + ar;
    int c0 = cb + (wn << 5) + ((lane & 3) << 1);
    #pragma unroll
    for (int s = 0; s < 4; s++) {
        int col = c0 + (s << 3);
        float v00 = acc[s][0], v01 = acc[s][1];   // row r0
        float v10 = acc[s][2], v11 = acc[s][3];   // row r0+8
        if (EPI == 5 && z == 0) {
            float2 rA = *(const float2*)&res[(size_t)r0 * Ntot + col];
            float2 rB = *(const float2*)&res[(size_t)(r0 + 8) * Ntot + col];
            v00 += rA.x; v01 += rA.y; v10 += rB.x; v11 += rB.y;
        }
        if (EPI == 2) {
            float b0v = bias[col], b1v = bias[col + 1];
            v00 += b0v; v01 += b1v; v10 += b0v; v11 += b1v;
            v00 = v00 / (1.0f + __expf(-v00));
            v01 = v01 / (1.0f + __expf(-v01));
            v10 = v10 / (1.0f + __expf(-v10));
            v11 = v11 / (1.0f + __expf(-v11));
        }
        *(float2*)&C[(size_t)r0 * Ntot + col]       = make_float2(v00, v01);
        *(float2*)&C[(size_t)(r0 + 8) * Ntot + col] = make_float2(v10, v11);
    }
}

// ====== FFMA2 GEMM (R11, proven): tile 32x128, BK=32, 256 threads — EPI3 only ====
// EPI 3: C = LN(res + A@B)*g + b   (attn o-proj)
template<int EPI>
__global__ void __launch_bounds__(256) gemm_kernel(
    const float* __restrict__ A, const float* __restrict__ B0,
    const float* __restrict__ B1, const float* __restrict__ B2,
    float* C0, float* C12, const float* res,
    int M, int K, int lda, int azk, int Ntot,
    const float* __restrict__ bias,
    const float* __restrict__ lng, const float* __restrict__ lnb)
{
    __shared__ __align__(16) float As[2][32 * 34];   // k-major, stride 34
    __shared__ __align__(16) float Bs[2][32][128];
    int z = blockIdx.z;
    const float* B = (z == 0) ? B0 : ((z == 1) ? B1 : B2);
    const float* Ab = A + (size_t)z * azk;
    float* C = C0;
    if (EPI == 0) C = C0 + (size_t)z * M * 128;

    int tid = threadIdx.x, tx = tid & 31, ty = tid >> 5;
    int m0 = blockIdx.y << 5, cb = blockIdx.x << 7;
    int nt = K >> 5;
    int am = tid >> 3, ak = (tid & 7) << 2;
    int brb = tid >> 5, bc4 = (tid & 31) << 2;

    float4 pa = *(const float4*)&Ab[(size_t)(m0 + am) * lda + ak];
    float4 pb[4];
    #pragma unroll
    for (int j = 0; j < 4; j++)
        pb[j] = *(const float4*)&B[(size_t)(brb + 8 * j) * Ntot + cb + bc4];
    As[0][(ak + 0) * 34 + am] = pa.x;
    As[0][(ak + 1) * 34 + am] = pa.y;
    As[0][(ak + 2) * 34 + am] = pa.z;
    As[0][(ak + 3) * 34 + am] = pa.w;
    #pragma unroll
    for (int j = 0; j < 4; j++)
        *(float4*)&Bs[0][brb + 8 * j][bc4] = pb[j];
    __syncthreads();

    ull c2[2][4];
    #pragma unroll
    for (int p = 0; p < 2; p++)
        #pragma unroll
        for (int c = 0; c < 4; c++) c2[p][c] = 0ULL;

    for (int t = 0; t < nt; t++) {
        int cur = t & 1;
        if (t + 1 < nt) {
            int k0 = (t + 1) << 5;
            pa = *(const float4*)&Ab[(size_t)(m0 + am) * lda + k0 + ak];
            #pragma unroll
            for (int j = 0; j < 4; j++)
                pb[j] = *(const float4*)&B[(size_t)(k0 + brb + 8 * j) * Ntot + cb + bc4];
        }
        const float* Ac = As[cur];
        #pragma unroll
        for (int k = 0; k < 32; k++) {
            float2 a01 = *(const float2*)&Ac[k * 34 + ty * 4];
            float2 a23 = *(const float2*)&Ac[k * 34 + ty * 4 + 2];
            float4 bv  = *(const float4*)&Bs[cur][k][tx << 2];
            ull A01 = pack2(a01.x, a01.y);
            ull A23 = pack2(a23.x, a23.y);
            ull D0 = dup2(bv.x), D1 = dup2(bv.y), D2 = dup2(bv.z), D3 = dup2(bv.w);
            c2[0][0] = fma2(A01, D0, c2[0][0]);  c2[1][0] = fma2(A23, D0, c2[1][0]);
            c2[0][1] = fma2(A01, D1, c2[0][1]);  c2[1][1] = fma2(A23, D1, c2[1][1]);
            c2[0][2] = fma2(A01, D2, c2[0][2]);  c2[1][2] = fma2(A23, D2, c2[1][2]);
            c2[0][3] = fma2(A01, D3, c2[0][3]);  c2[1][3] = fma2(A23, D3, c2[1][3]);
        }
        if (t + 1 < nt) {
            int nb = cur ^ 1;
            As[nb][(ak + 0) * 34 + am] = pa.x;
            As[nb][(ak + 1) * 34 + am] = pa.y;
            As[nb][(ak + 2) * 34 + am] = pa.z;
            As[nb][(ak + 3) * 34 + am] = pa.w;
            #pragma unroll
            for (int j = 0; j < 4; j++)
                *(float4*)&Bs[nb][brb + 8 * j][bc4] = pb[j];
        }
        __syncthreads();
    }

    float val[4][4];
    #pragma unroll
    for (int p = 0; p < 2; p++)
        #pragma unroll
        for (int c = 0; c < 4; c++) {
            float2 u = unpk(c2[p][c]);
            val[2*p + 0][c] = u.x;
            val[2*p + 1][c] = u.y;
        }
    int cg = cb + (tx << 2);
    int r0 = m0 + ty * 4;

    // EPI 3: residual, row LayerNorm (warp owns full rows)
    #pragma unroll
    for (int i = 0; i < 4; i++) {
        float4 rv = *(const float4*)&res[(size_t)(r0 + i) * 128 + cg];
        val[i][0] += rv.x;  val[i][1] += rv.y;
        val[i][2] += rv.z;  val[i][3] += rv.w;
    }
    float s[4], sq[4];
    #pragma unroll
    for (int i = 0; i < 4; i++) {
        s[i]  = val[i][0] + val[i][1] + val[i][2] + val[i][3];
        sq[i] = val[i][0]*val[i][0] + val[i][1]*val[i][1]
              + val[i][2]*val[i][2] + val[i][3]*val[i][3];
    }
    #pragma unroll
    for (int o = 16; o > 0; o >>= 1) {
        #pragma unroll
        for (int i = 0; i < 4; i++) {
            s[i]  += __shfl_xor_sync(0xffffffffu, s[i],  o);
            sq[i] += __shfl_xor_sync(0xffffffffu, sq[i], o);
        }
    }
    float4 g4 = *(const float4*)&lng[cg];
    float4 b4 = *(const float4*)&lnb[cg];
    #pragma unroll
    for (int i = 0; i < 4; i++) {
        float mean = s[i] * (1.0f / 128.0f);
        float var  = fmaxf(sq[i] * (1.0f / 128.0f) - mean * mean, 0.0f);
        float rstd = rsqrtf(var + 1e-5f);
        float h0 = (val[i][0] - mean) * rstd * g4.x + b4.x;
        float h1 = (val[i][1] - mean) * rstd * g4.y + b4.y;
        float h2 = (val[i][2] - mean) * rstd * g4.z + b4.z;
        float h3 = (val[i][3] - mean) * rstd * g4.w + b4.w;
        *(float4*)&C[(size_t)(r0 + i) * 128 + cg] = make_float4(h0, h1, h2, h3);
    }
}

// ---- FF2 epilogue: t = LN(h + part0 + part1 + b2)*g + b; gate = tanh(t@Wc+bc);
//      x += gate*(x-px); px = 0; h = t (+ next layer's rbfW)
__global__ void __launch_bounds__(128) ff2_epi_kernel(
    const float* __restrict__ part, float* __restrict__ h,
    const float* __restrict__ b2,
    const float* __restrict__ g, const float* __restrict__ b,
    const float* __restrict__ Wc, const float* __restrict__ bc,
    float* __restrict__ px, float* __restrict__ x,
    const float* __restrict__ extra)
{
    int row = blockIdx.x, tid = threadIdx.x;
    int idx = row * 128 + tid;
    float t = h[idx] + part[idx] + part[E_ * 128 + idx] + b2[tid];
    float s = t, sq = t * t;
    #pragma unroll
    for (int o = 16; o > 0; o >>= 1) {
        s  += __shfl_xor_sync(0xffffffffu, s,  o);
        sq += __shfl_xor_sync(0xffffffffu, sq, o);
    }
    __shared__ float ss[4], sqs[4], gs[4];
    if ((tid & 31) == 0) { ss[tid >> 5] = s; sqs[tid >> 5] = sq; }
    __syncthreads();
    float S  = ss[0] + ss[1] + ss[2] + ss[3];
    float SQ = sqs[0] + sqs[1] + sqs[2] + sqs[3];
    float mean = S * (1.0f / 128.0f);
    float var = fmaxf(SQ * (1.0f / 128.0f) - mean * mean, 0.0f);
    float rstd = rsqrtf(var + 1e-5f);
    float hn = (t - mean) * rstd * g[tid] + b[tid];
    float gp = hn * Wc[tid];
    #pragma unroll
    for (int o = 16; o > 0; o >>= 1) gp += __shfl_xor_sync(0xffffffffu, gp, o);
    if ((tid & 31) == 0) gs[tid >> 5] = gp;
    __syncthreads();
    h[idx] = hn + (extra ? extra[idx] : 0.0f);
    if (tid < 3) {
        float gd = gs[0] + gs[1] + gs[2] + gs[3];
        float gt = tanhf(gd + bc[0]);
        float xv = x[row * 3 + tid];
        float pv = px[row * 3 + tid];
        x[row * 3 + tid]  = xv + gt * (xv - pv);
        px[row * 3 + tid] = 0.0f;   // ready for next layer / next replay
    }
}

// ---------------- sparse masked attention (unchanged, proven) ----------------
template<bool INTRA>
__global__ void __launch_bounds__(256) attn_kernel(
    const float* __restrict__ q, const float* __restrict__ k, const float* __restrict__ v,
    const float* __restrict__ x, float* __restrict__ out, float* __restrict__ px)
{
    int warp = threadIdx.x >> 5, lane = threadIdx.x & 31;
    int i = blockIdx.x * 8 + warp;
    int head = blockIdx.y;
    int off = head * HD_;
    int d = lane & 15, half = lane >> 4;
    unsigned hm = half ? 0xffff0000u : 0x0000ffffu;   // lanes of MY half only

    float qd = q[i * D_ + off + d];
    int n = INTRA ? g_icnt[i] : g_xcnt[i];
    const int* li = (INTRA ? g_ilist : g_xlist) + i * CAP_;

    float m = -1e30f, l = 0.0f, acc = 0.0f, ax = 0.0f;

    for (int t = half; t < n; t += 2) {
        int j = li[t];
        float s = qd * k[j * D_ + off + d];
        s += __shfl_xor_sync(hm, s, 8);
        s += __shfl_xor_sync(hm, s, 4);
        s += __shfl_xor_sync(hm, s, 2);
        s += __shfl_xor_sync(hm, s, 1);
        s *= 0.25f;  // 1/sqrt(16)
        float vd = v[j * D_ + off + d];
        float mn = fmaxf(m, s);
        float cc = __expf(m - mn), p = __expf(s - mn);
        l = l * cc + p;
        acc = acc * cc + p * vd;
        if (INTRA && d < 3) ax = ax * cc + p * x[j * 3 + d];
        m = mn;
    }

    float m2 = __shfl_xor_sync(0xffffffffu, m, 16);
    float l2 = __shfl_xor_sync(0xffffffffu, l, 16);
    float a2 = __shfl_xor_sync(0xffffffffu, acc, 16);
    float mn = fmaxf(m, m2);
    float c1 = __expf(m - mn), c2 = __expf(m2 - mn);
    l = l * c1 + l2 * c2;
    acc = acc * c1 + a2 * c2;
    if (INTRA) {
        float x2 = __shfl_xor_sync(0xffffffffu, ax, 16);
        ax = ax * c1 + x2 * c2;
    }
    float inv = 1.0f / l;  // diag always present -> l > 0
    if (half == 0) {
        out[i * D_ + off + d] = acc * inv;
        if (INTRA && d < 3) atomicAdd(&px[i * 3 + d], ax * inv * 0.125f);
    }
}

// ---------------- output: concat(h, x) ----------------
__global__ void out_kernel(const float* __restrict__ h, const float* __restrict__ x,
                           float* __restrict__ out, int out_size)
{
    int i = blockIdx.x * 256 + threadIdx.x;
    if (i >= out_size) return;
    if (i < E_ * D_)               out[i] = h[i];
    else if (i < E_ * D_ + E_ * 3) out[i] = x[i - E_ * D_];
    else                           out[i] = 0.0f;
}

// ---------------- host ----------------
extern "C" void kernel_launch(void* const* d_in, const int* in_sizes, int n_in,
                              void* d_out, int out_size)
{
    const float* edge_features = (const float*)d_in[0];
    const float* edge_coords   = (const float*)d_in[1];
    const int*   edge_index    = (const int*)  d_in[2];
    const float* node_coords   = (const float*)d_in[3];
    const int*   block_ids     = (const int*)  d_in[4];
    const float* Wq_a = (const float*)d_in[5];
    const float* Wk_a = (const float*)d_in[6];
    const float* Wv_a = (const float*)d_in[7];
    const float* Wo_a = (const float*)d_in[8];
    const float* Wq_e = (const float*)d_in[9];
    const float* Wk_e = (const float*)d_in[10];
    const float* Wv_e = (const float*)d_in[11];
    const float* Wo_e = (const float*)d_in[12];
    const float* W1   = (const float*)d_in[13];
    const float* b1   = (const float*)d_in[14];
    const float* W2   = (const float*)d_in[15];
    const float* b2   = (const float*)d_in[16];
    const float* ln1g = (const float*)d_in[17];
    const float* ln1b = (const float*)d_in[18];
    const float* ln2g = (const float*)d_in[19];
    const float* ln2b = (const float*)d_in[20];
    const float* ln3g = (const float*)d_in[21];
    const float* ln3b = (const float*)d_in[22];
    const float* Wrbf = (const float*)d_in[23];
    const float* Wc   = (const float*)d_in[24];
    const float* bc   = (const float*)d_in[25];

    float* buf = nullptr;
    cudaGetSymbolAddress((void**)&buf, g_buf);
    float* h    = buf + OFF_H;
    float* qb   = buf + OFF_Q;
    float* kb   = qb + E_ * D_;
    float* vb   = qb + 2 * E_ * D_;
    float* att  = buf + OFF_ATT;
    float* mid  = buf + OFF_MID;
    float* rbf  = buf + OFF_RBF;
    float* px   = buf + OFF_PX;
    float* xb   = buf + OFF_X;
    int4*  meta = (int4*)(buf + OFF_META);
    float* rbfW = buf + OFF_RBFW;   // rbfW for layers 1,2 (layer 0 folds into h)
    float* part = buf + OFF_PART;   // FF2 split-K partials

    dim3 g1(1, E_ / 32, 1);          // 96 blocks
    dim3 g3(1, E_ / 32, 3);          // 288 blocks
    dim3 gF(FF_ / 128, E_ / 32, 1);  // 384 blocks
    dim3 g2(1, E_ / 32, 2);          // 192 blocks (FF2 split-K)
    dim3 gAttn(E_ / 8, H_);          // 384 blocks

    prep_kernel<<<(E_ + 127) / 128, 128>>>(edge_index, block_ids, node_coords,
                                           edge_coords, meta, rbf, px, xb);
    build_kernel<<<E_, 128>>>(meta);

    // rbfW_l = rbf @ Wrbf[l] for all 3 layers in one launch (tensor cores).
    // z=0 -> h = edge_features + rbfW_0 (layer-0 h'); z=1,2 -> rbfW buffers.
    mma_gemm<5><<<g3, 256>>>(rbf, Wrbf, Wrbf + R_ * D_, Wrbf + 2 * R_ * D_,
                             h, rbfW, edge_features, E_, R_, R_, 0, D_, nullptr);

    for (int l = 0; l < L_; l++) {
        const int DD = D_ * D_;
        const float* nextRbfW = (l < 2) ? (rbfW + (size_t)l * E_ * D_) : nullptr;

        // --- intra attention (QKV on tensor cores) ---
        mma_gemm<0><<<g3, 256>>>(h, Wq_a + l * DD, Wk_a + l * DD, Wv_a + l * DD,
                                 qb, nullptr, nullptr, E_, D_, D_, 0, D_, nullptr);
        attn_kernel<true><<<gAttn, 256>>>(qb, kb, vb, xb, att, px);
        gemm_kernel<3><<<g1, 256>>>(att, Wo_a + l * DD, nullptr, nullptr,
                                    h, nullptr, h, E_, D_, D_, 0, D_,
                                    nullptr, ln1g + l * D_, ln1b + l * D_);

        // --- inter attention ---
        mma_gemm<0><<<g3, 256>>>(h, Wq_e + l * DD, Wk_e + l * DD, Wv_e + l * DD,
                                 qb, nullptr, nullptr, E_, D_, D_, 0, D_, nullptr);
        attn_kernel<false><<<gAttn, 256>>>(qb, kb, vb, xb, att, nullptr);
        gemm_kernel<3><<<g1, 256>>>(att, Wo_e + l * DD, nullptr, nullptr,
                                    h, nullptr, h, E_, D_, D_, 0, D_,
                                    nullptr, ln2g + l * D_, ln2b + l * D_);

        // --- FFN: up-proj (silu, tensor cores), split-K down-proj (tensor cores) ---
        mma_gemm<2><<<gF, 256>>>(h, W1 + (size_t)l * D_ * FF_, nullptr, nullptr,
                                 mid, nullptr, nullptr, E_, D_, D_, 0, FF_,
                                 b1 + l * FF_);
        mma_gemm<0><<<g2, 256>>>(mid, W2 + (size_t)l * FF_ * D_,
                                 W2 + (size_t)l * FF_ * D_ + 256 * D_, nullptr,
                                 part, nullptr, nullptr, E_, 256, FF_, 256, D_,
                                 nullptr);
        ff2_epi_kernel<<<E_, 128>>>(part, h, b2 + l * D_,
                                    ln3g + l * D_, ln3b + l * D_,
                                    Wc + l * D_, bc + l, px, xb, nextRbfW);
    }

    out_kernel<<<(out_size + 255) / 256, 256>>>(h, xb, (float*)d_out, out_size);
}

// round 16
// speedup vs baseline: 1.2784x; 1.0765x over previous
#include <cuda_runtime.h>
#include <cuda_bf16.h>
#include <math.h>

#define E_   3072
#define D_   128
#define H_   8
#define HD_  16
#define R_   64
#define FF_  512
#define L_   3
#define CAP_ 128

// ---------------- scratch (no allocations allowed) ----------------
#define OFF_H    0
#define OFF_Q    393216          // q,k,v contiguous
#define OFF_ATT  1572864
#define OFF_MID  2359296
#define OFF_RBF  3932160
#define OFF_PX   4128768
#define OFF_X    4137984
#define OFF_META 4147200
#define OFF_RBFW 4159488
#define OFF_PART 4945920         // FF2 split-K partials: 2 x E x 128
#define OFF_WHI  5732352         // pre-split weights, hi bf16 k-pair packed (u32)
#define OFF_WLO  6137856         // lo half
#define TOTAL_F  6543360

// pre-split weight offsets (u32 units)
// families t: 0=Wq_a 1=Wk_a 2=Wv_a 3=Wo_a 4=Wq_e 5=Wk_e 6=Wv_e 7=Wo_e
#define WQKV(t, l)  ((t) * 24576 + (l) * 8192)
#define WW1(l)      (196608 + (l) * 32768)
#define WW2(l, z)   (294912 + (l) * 32768 + (z) * 16384)
#define WRBF(l)     (393216 + (l) * 4096)

__device__ __align__(16) float g_buf[TOTAL_F];
__device__ int g_ilist[E_ * CAP_];
__device__ int g_xlist[E_ * CAP_];
__device__ int g_icnt[E_];
__device__ int g_xcnt[E_];

// ---------------- bf16 split helpers ----------------
__device__ __forceinline__ void split2(float x, float y, unsigned& hi, unsigned& lo) {
    __nv_bfloat16 hx = __float2bfloat16(x), hy = __float2bfloat16(y);
    __nv_bfloat16 lx = __float2bfloat16(x - __bfloat162float(hx));
    __nv_bfloat16 ly = __float2bfloat16(y - __bfloat162float(hy));
    hi = (unsigned)__bfloat16_as_ushort(hx) | ((unsigned)__bfloat16_as_ushort(hy) << 16);
    lo = (unsigned)__bfloat16_as_ushort(lx) | ((unsigned)__bfloat16_as_ushort(ly) << 16);
}

// warp-level MMA m16n8k16 bf16 -> f32 accumulate (sm_80+, valid on sm_100)
__device__ __forceinline__ void mma16816(float* c, unsigned a0, unsigned a1,
                                         unsigned a2, unsigned a3,
                                         unsigned b0, unsigned b1) {
    asm volatile(
        "mma.sync.aligned.m16n8k16.row.col.f32.bf16.bf16.f32 "
        "{%0,%1,%2,%3}, {%4,%5,%6,%7}, {%8,%9}, {%0,%1,%2,%3};"
        : "+f"(c[0]), "+f"(c[1]), "+f"(c[2]), "+f"(c[3])
        : "r"(a0), "r"(a1), "r"(a2), "r"(a3), "r"(b0), "r"(b1));
}

// ---------------- weight pre-split: fp32 [l][k][n] -> packed k-pair bf16 hi/lo ----
// u32 idx p within a region: n = p % N; f0 = 2p - n; pair = (src[f0], src[f0+N]).
__global__ void __launch_bounds__(256) wsplit_kernel(
    const float* __restrict__ Wq_a, const float* __restrict__ Wk_a,
    const float* __restrict__ Wv_a, const float* __restrict__ Wo_a,
    const float* __restrict__ Wq_e, const float* __restrict__ Wk_e,
    const float* __restrict__ Wv_e, const float* __restrict__ Wo_e,
    const float* __restrict__ W1,  const float* __restrict__ W2,
    const float* __restrict__ Wrbf,
    unsigned* __restrict__ whi, unsigned* __restrict__ wlo)
{
    int reg = blockIdx.y;
    int p = blockIdx.x * 256 + threadIdx.x;
    const float* src;
    int N, npairs, base;
    if (reg < 8) {
        const float* fam[8] = { Wq_a, Wk_a, Wv_a, Wo_a, Wq_e, Wk_e, Wv_e, Wo_e };
        src = fam[reg]; N = 128; npairs = 24576; base = reg * 24576;
    } else if (reg == 8)  { src = W1;   N = 512; npairs = 98304; base = 196608; }
    else if (reg == 9)    { src = W2;   N = 128; npairs = 98304; base = 294912; }
    else                  { src = Wrbf; N = 128; npairs = 12288; base = 393216; }
    if (p >= npairs) return;
    int n = p % N;
    size_t f0 = 2 * (size_t)p - n;
    unsigned hi, lo;
    split2(src[f0], src[f0 + N], hi, lo);
    whi[base + p] = hi;
    wlo[base + p] = lo;
}

// ---------------- prep: edge meta + rbf + zero px + copy x ----------------
__global__ void prep_kernel(const int* __restrict__ ei, const int* __restrict__ bid,
                            const float* __restrict__ nc, const float* __restrict__ ec,
                            int4* __restrict__ meta, float* __restrict__ rbf,
                            float* __restrict__ px, float* __restrict__ xb) {
    int e = blockIdx.x * 128 + threadIdx.x;
    if (e >= E_) return;
    int s = ei[e], d = ei[E_ + e];
    meta[e] = make_int4(s, d, bid[s], bid[d]);
    px[e*3+0] = 0.f; px[e*3+1] = 0.f; px[e*3+2] = 0.f;
    xb[e*3+0] = ec[e*3+0]; xb[e*3+1] = ec[e*3+1]; xb[e*3+2] = ec[e*3+2];
    float dx = nc[d*3+0] - nc[s*3+0];
    float dy = nc[d*3+1] - nc[s*3+1];
    float dz = nc[d*3+2] - nc[s*3+2];
    float dist = sqrtf(dx*dx + dy*dy + dz*dz);
    float t = fminf(dist * 0.1f, 1.0f);
    float fc = 0.5f * (cosf(3.14159265358979323846f * t) + 1.0f);
    const float inw = 64.0f / 10.0f;   // 1/width, width = CUTOFF/R
    #pragma unroll 8
    for (int r = 0; r < R_; r++) {
        float c = 10.0f * (float)r / 63.0f;   // linspace(0,10,64)
        float u = (dist - c) * inw;
        rbf[e * R_ + r] = expf(-u * u) * fc;
    }
}

// ---------------- build neighbor lists (once; layer/head-invariant) ----------
__global__ void __launch_bounds__(128) build_kernel(const int4* __restrict__ meta) {
    __shared__ int ci, cx;
    int i = blockIdx.x, tid = threadIdx.x;
    if (tid == 0) { ci = 0; cx = 0; }
    __syncthreads();
    int4 mi = meta[i];
    for (int j = tid; j < E_; j += 128) {
        int4 mj = meta[j];
        bool ip = (mi.z == mj.z) && (mi.w == mj.w);
        bool share = (mi.x == mj.x) || (mi.x == mj.y) || (mi.y == mj.x) || (mi.y == mj.y);
        if (ip || (i == j)) {
            int p = atomicAdd(&ci, 1);
            if (p < CAP_) g_ilist[i * CAP_ + p] = j;
        }
        if ((share && !ip) || (i == j)) {
            int p = atomicAdd(&cx, 1);
            if (p < CAP_) g_xlist[i * CAP_ + p] = j;
        }
    }
    __syncthreads();
    if (tid == 0) {
        g_icnt[i] = min(ci, CAP_);
        g_xcnt[i] = min(cx, CAP_);
    }
}

// ====== tensor-core GEMM via mma.sync bf16 split-3: tile 32x128, BK=32 ==========
// A fp32 split on staging; B pre-split (whi/wlo + per-z u32 offset).
// Accumulates hiA*hiB + hiA*loB + loA*hiB in f32.
// 256 threads = 8 warps laid out 2(m) x 4(n); warp: 16 rows x 32 cols.
// EPI 0: C = A@B; z selects off, C = C0 + z*M*128   (QKV / FF2 split-K parts)
// EPI 5: z selects off; C = A@B (+res if z==0); z=0 -> C0, z>0 -> C12+(z-1)*M*128
// EPI 2: C = silu(A@B + bias)                       (FFN up)
// EPI 3: C = LN(res + A@B)*g + b                    (attn o-proj; smem roundtrip)
template<int EPI>
__global__ void __launch_bounds__(256) mma_gemm(
    const float* __restrict__ A,
    const unsigned* __restrict__ whi, const unsigned* __restrict__ wlo,
    int off0, int off1, int off2,
    float* C0, float* C12, const float* res,
    int M, int K, int lda, int azk, int Ntot,
    const float* __restrict__ bias,
    const float* __restrict__ lng, const float* __restrict__ lnb)
{
    // carved smem: AsHi[2][640] AsLo[2][640] BsHi[2][2176] BsLo[2][2176] (u32)
    __shared__ __align__(16) unsigned SB[11264];
    unsigned* AsHi = SB;
    unsigned* AsLo = SB + 1280;
    unsigned* BsHi = SB + 2560;
    unsigned* BsLo = SB + 6912;

    int z = blockIdx.z;
    int woff = (z == 0) ? off0 : ((z == 1) ? off1 : off2);
    const unsigned* Bh = whi + woff;
    const unsigned* Bl = wlo + woff;
    const float* Ab = A + (size_t)z * azk;
    float* C;
    if (EPI == 0)      C = C0 + (size_t)z * M * 128;
    else if (EPI == 5) C = (z == 0) ? C0 : (C12 + (size_t)(z - 1) * M * 128);
    else               C = C0;

    int tid = threadIdx.x, lane = tid & 31, wid = tid >> 5;
    int m0 = blockIdx.y << 5, cb = blockIdx.x << 7;
    int nt = K >> 5;

    int am = tid >> 3, ak4 = (tid & 7) << 2;      // A: one float4 per thread
    int k2i = (tid & 7) << 1;                      // k-pair index of that float4

    int wm = wid >> 2, wn = wid & 3;
    int ar = (wm << 4) + (lane >> 2);              // A row (a0); a1 at +8
    int ac = lane & 3;
    int bcc = (wn << 5) + (lane >> 2);
    int bk = lane & 3;

    // ---- prologue: stage tile 0 into buffer 0
    {
        float4 a4 = *(const float4*)&Ab[(size_t)(m0 + am) * lda + ak4];
        unsigned h0, l0, h1, l1;
        split2(a4.x, a4.y, h0, l0);
        split2(a4.z, a4.w, h1, l1);
        AsHi[am * 20 + k2i] = h0;  AsHi[am * 20 + k2i + 1] = h1;
        AsLo[am * 20 + k2i] = l0;  AsLo[am * 20 + k2i + 1] = l1;
        #pragma unroll
        for (int j = 0; j < 2; j++) {
            int u = tid + (j << 8);
            int bk2 = u >> 5, bn4 = (u & 31) << 2;
            uint4 hv = *(const uint4*)&Bh[(size_t)bk2 * Ntot + cb + bn4];
            uint4 lv = *(const uint4*)&Bl[(size_t)bk2 * Ntot + cb + bn4];
            *(uint4*)&BsHi[bk2 * 136 + bn4] = hv;
            *(uint4*)&BsLo[bk2 * 136 + bn4] = lv;
        }
    }
    __syncthreads();

    float acc[4][4];
    #pragma unroll
    for (int s = 0; s < 4; s++)
        #pragma unroll
        for (int c = 0; c < 4; c++) acc[s][c] = 0.0f;

    for (int t = 0; t < nt; t++) {
        int cur = t & 1;
        unsigned aco = cur * 640, bco = cur * 2176;
        float4 apf;
        uint4 bph[2], bpl[2];
        if (t + 1 < nt) {               // register prefetch overlaps compute
            int k0 = (t + 1) << 5;
            int k2b = (t + 1) << 4;
            apf = *(const float4*)&Ab[(size_t)(m0 + am) * lda + k0 + ak4];
            #pragma unroll
            for (int j = 0; j < 2; j++) {
                int u = tid + (j << 8);
                int bk2 = u >> 5, bn4 = (u & 31) << 2;
                bph[j] = *(const uint4*)&Bh[(size_t)(k2b + bk2) * Ntot + cb + bn4];
                bpl[j] = *(const uint4*)&Bl[(size_t)(k2b + bk2) * Ntot + cb + bn4];
            }
        }
        #pragma unroll
        for (int ks = 0; ks < 2; ks++) {
            int k2b = ks << 3;
            unsigned aH0 = AsHi[aco +  ar      * 20 + k2b + ac];
            unsigned aH1 = AsHi[aco + (ar + 8) * 20 + k2b + ac];
            unsigned aH2 = AsHi[aco +  ar      * 20 + k2b + 4 + ac];
            unsigned aH3 = AsHi[aco + (ar + 8) * 20 + k2b + 4 + ac];
            unsigned aL0 = AsLo[aco +  ar      * 20 + k2b + ac];
            unsigned aL1 = AsLo[aco + (ar + 8) * 20 + k2b + ac];
            unsigned aL2 = AsLo[aco +  ar      * 20 + k2b + 4 + ac];
            unsigned aL3 = AsLo[aco + (ar + 8) * 20 + k2b + 4 + ac];
            #pragma unroll
            for (int s = 0; s < 4; s++) {
                int bi0 = bco + (k2b + bk) * 136 + bcc + (s << 3);
                int bi1 = bco + (k2b + 4 + bk) * 136 + bcc + (s << 3);
                unsigned bH0 = BsHi[bi0], bH1 = BsHi[bi1];
                unsigned bL0 = BsLo[bi0], bL1 = BsLo[bi1];
                mma16816(acc[s], aH0, aH1, aH2, aH3, bH0, bH1);
                mma16816(acc[s], aH0, aH1, aH2, aH3, bL0, bL1);
                mma16816(acc[s], aL0, aL1, aL2, aL3, bH0, bH1);
            }
        }
        if (t + 1 < nt) {
            int nb = cur ^ 1;
            unsigned ano = nb * 640, bno = nb * 2176;
            unsigned h0, l0, h1, l1;
            split2(apf.x, apf.y, h0, l0);
            split2(apf.z, apf.w, h1, l1);
            AsHi[ano + am * 20 + k2i] = h0;  AsHi[ano + am * 20 + k2i + 1] = h1;
            AsLo[ano + am * 20 + k2i] = l0;  AsLo[ano + am * 20 + k2i + 1] = l1;
            #pragma unroll
            for (int j = 0; j < 2; j++) {
                int u = tid + (j << 8);
                int bk2 = u >> 5, bn4 = (u & 31) << 2;
                *(uint4*)&BsHi[bno + bk2 * 136 + bn4] = bph[j];
                *(uint4*)&BsLo[bno + bk2 * 136 + bn4] = bpl[j];
            }
        }
        __syncthreads();
    }

    if (EPI == 3) {
        // spill acc to smem tile [32][132] (reuses staging smem; loop ended w/ sync)
        float* tile = (float*)SB;
        int c0l = (wn << 5) + ((lane & 3) << 1);
        #pragma unroll
        for (int s = 0; s < 4; s++) {
            int col = c0l + (s << 3);
            tile[ar * 132 + col]           = acc[s][0];
            tile[ar * 132 + col + 1]       = acc[s][1];
            tile[(ar + 8) * 132 + col]     = acc[s][2];
            tile[(ar + 8) * 132 + col + 1] = acc[s][3];
        }
        __syncthreads();
        // proven row-LN epilogue: warp ty owns rows 4ty..4ty+3 (full rows)
        int tx = tid & 31, ty = tid >> 5;
        int cg = tx << 2;
        int r0 = m0 + ty * 4;
        float val[4][4];
        float s_[4], sq[4];
        #pragma unroll
        for (int i = 0; i < 4; i++) {
            float4 v = *(float4*)&tile[(ty * 4 + i) * 132 + cg];
            float4 rv = *(const float4*)&res[(size_t)(r0 + i) * 128 + cg];
            val[i][0] = v.x + rv.x;  val[i][1] = v.y + rv.y;
            val[i][2] = v.z + rv.z;  val[i][3] = v.w + rv.w;
            s_[i] = val[i][0] + val[i][1] + val[i][2] + val[i][3];
            sq[i] = val[i][0]*val[i][0] + val[i][1]*val[i][1]
                  + val[i][2]*val[i][2] + val[i][3]*val[i][3];
        }
        #pragma unroll
        for (int o = 16; o > 0; o >>= 1) {
            #pragma unroll
            for (int i = 0; i < 4; i++) {
                s_[i] += __shfl_xor_sync(0xffffffffu, s_[i], o);
                sq[i] += __shfl_xor_sync(0xffffffffu, sq[i], o);
            }
        }
        float4 g4 = *(const float4*)&lng[cg];
        float4 b4 = *(const float4*)&lnb[cg];
        #pragma unroll
        for (int i = 0; i < 4; i++) {
            float mean = s_[i] * (1.0f / 128.0f);
            float var  = fmaxf(sq[i] * (1.0f / 128.0f) - mean * mean, 0.0f);
            float rstd = rsqrtf(var + 1e-5f);
            float h0 = (val[i][0] - mean) * rstd * g4.x + b4.x;
            float h1 = (val[i][1] - mean) * rstd * g4.y + b4.y;
            float h2 = (val[i][2] - mean) * rstd * g4.z + b4.z;
            float h3 = (val[i][3] - mean) * rstd * g4.w + b4.w;
            *(float4*)&C[(size_t)(r0 + i) * 128 + cg] = make_float4(h0, h1, h2, h3);
        }
        return;
    }

    // ---- direct epilogues: lane holds rows r0, r0+8; cols c0+s*8, +1
    int r0 = m0 + ar;
    int c0 = cb + (wn << 5) + ((lane & 3) << 1);
    #pragma unroll
    for (int s = 0; s < 4; s++) {
        int col = c0 + (s << 3);
        float v00 = acc[s][0], v01 = acc[s][1];   // row r0
        float v10 = acc[s][2], v11 = acc[s][3];   // row r0+8
        if (EPI == 5 && z == 0) {
            float2 rA = *(const float2*)&res[(size_t)r0 * Ntot + col];
            float2 rB = *(const float2*)&res[(size_t)(r0 + 8) * Ntot + col];
            v00 += rA.x; v01 += rA.y; v10 += rB.x; v11 += rB.y;
        }
        if (EPI == 2) {
            float b0v = bias[col], b1v = bias[col + 1];
            v00 += b0v; v01 += b1v; v10 += b0v; v11 += b1v;
            v00 = v00 / (1.0f + __expf(-v00));
            v01 = v01 / (1.0f + __expf(-v01));
            v10 = v10 / (1.0f + __expf(-v10));
            v11 = v11 / (1.0f + __expf(-v11));
        }
        *(float2*)&C[(size_t)r0 * Ntot + col]       = make_float2(v00, v01);
        *(float2*)&C[(size_t)(r0 + 8) * Ntot + col] = make_float2(v10, v11);
    }
}

// ---- FF2 epilogue: t = LN(h + part0 + part1 + b2)*g + b; gate = tanh(t@Wc+bc);
//      x += gate*(x-px); px = 0; h = t (+ next layer's rbfW)
__global__ void __launch_bounds__(128) ff2_epi_kernel(
    const float* __restrict__ part, float* __restrict__ h,
    const float* __restrict__ b2,
    const float* __restrict__ g, const float* __restrict__ b,
    const float* __restrict__ Wc, const float* __restrict__ bc,
    float* __restrict__ px, float* __restrict__ x,
    const float* __restrict__ extra)
{
    int row = blockIdx.x, tid = threadIdx.x;
    int idx = row * 128 + tid;
    float t = h[idx] + part[idx] + part[E_ * 128 + idx] + b2[tid];
    float s = t, sq = t * t;
    #pragma unroll
    for (int o = 16; o > 0; o >>= 1) {
        s  += __shfl_xor_sync(0xffffffffu, s,  o);
        sq += __shfl_xor_sync(0xffffffffu, sq, o);
    }
    __shared__ float ss[4], sqs[4], gs[4];
    if ((tid & 31) == 0) { ss[tid >> 5] = s; sqs[tid >> 5] = sq; }
    __syncthreads();
    float S  = ss[0] + ss[1] + ss[2] + ss[3];
    float SQ = sqs[0] + sqs[1] + sqs[2] + sqs[3];
    float mean = S * (1.0f / 128.0f);
    float var = fmaxf(SQ * (1.0f / 128.0f) - mean * mean, 0.0f);
    float rstd = rsqrtf(var + 1e-5f);
    float hn = (t - mean) * rstd * g[tid] + b[tid];
    float gp = hn * Wc[tid];
    #pragma unroll
    for (int o = 16; o > 0; o >>= 1) gp += __shfl_xor_sync(0xffffffffu, gp, o);
    if ((tid & 31) == 0) gs[tid >> 5] = gp;
    __syncthreads();
    h[idx] = hn + (extra ? extra[idx] : 0.0f);
    if (tid < 3) {
        float gd = gs[0] + gs[1] + gs[2] + gs[3];
        float gt = tanhf(gd + bc[0]);
        float xv = x[row * 3 + tid];
        float pv = px[row * 3 + tid];
        x[row * 3 + tid]  = xv + gt * (xv - pv);
        px[row * 3 + tid] = 0.0f;   // ready for next layer / next replay
    }
}

// ---------------- sparse masked attention (unchanged, proven) ----------------
template<bool INTRA>
__global__ void __launch_bounds__(256) attn_kernel(
    const float* __restrict__ q, const float* __restrict__ k, const float* __restrict__ v,
    const float* __restrict__ x, float* __restrict__ out, float* __restrict__ px)
{
    int warp = threadIdx.x >> 5, lane = threadIdx.x & 31;
    int i = blockIdx.x * 8 + warp;
    int head = blockIdx.y;
    int off = head * HD_;
    int d = lane & 15, half = lane >> 4;
    unsigned hm = half ? 0xffff0000u : 0x0000ffffu;   // lanes of MY half only

    float qd = q[i * D_ + off + d];
    int n = INTRA ? g_icnt[i] : g_xcnt[i];
    const int* li = (INTRA ? g_ilist : g_xlist) + i * CAP_;

    float m = -1e30f, l = 0.0f, acc = 0.0f, ax = 0.0f;

    for (int t = half; t < n; t += 2) {
        int j = li[t];
        float s = qd * k[j * D_ + off + d];
        s += __shfl_xor_sync(hm, s, 8);
        s += __shfl_xor_sync(hm, s, 4);
        s += __shfl_xor_sync(hm, s, 2);
        s += __shfl_xor_sync(hm, s, 1);
        s *= 0.25f;  // 1/sqrt(16)
        float vd = v[j * D_ + off + d];
        float mn = fmaxf(m, s);
        float cc = __expf(m - mn), p = __expf(s - mn);
        l = l * cc + p;
        acc = acc * cc + p * vd;
        if (INTRA && d < 3) ax = ax * cc + p * x[j * 3 + d];
        m = mn;
    }

    float m2 = __shfl_xor_sync(0xffffffffu, m, 16);
    float l2 = __shfl_xor_sync(0xffffffffu, l, 16);
    float a2 = __shfl_xor_sync(0xffffffffu, acc, 16);
    float mn = fmaxf(m, m2);
    float c1 = __expf(m - mn), c2 = __expf(m2 - mn);
    l = l * c1 + l2 * c2;
    acc = acc * c1 + a2 * c2;
    if (INTRA) {
        float x2 = __shfl_xor_sync(0xffffffffu, ax, 16);
        ax = ax * c1 + x2 * c2;
    }
    float inv = 1.0f / l;  // diag always present -> l > 0
    if (half == 0) {
        out[i * D_ + off + d] = acc * inv;
        if (INTRA && d < 3) atomicAdd(&px[i * 3 + d], ax * inv * 0.125f);
    }
}

// ---------------- output: concat(h, x) ----------------
__global__ void out_kernel(const float* __restrict__ h, const float* __restrict__ x,
                           float* __restrict__ out, int out_size)
{
    int i = blockIdx.x * 256 + threadIdx.x;
    if (i >= out_size) return;
    if (i < E_ * D_)               out[i] = h[i];
    else if (i < E_ * D_ + E_ * 3) out[i] = x[i - E_ * D_];
    else                           out[i] = 0.0f;
}

// ---------------- host ----------------
extern "C" void kernel_launch(void* const* d_in, const int* in_sizes, int n_in,
                              void* d_out, int out_size)
{
    const float* edge_features = (const float*)d_in[0];
    const float* edge_coords   = (const float*)d_in[1];
    const int*   edge_index    = (const int*)  d_in[2];
    const float* node_coords   = (const float*)d_in[3];
    const int*   block_ids     = (const int*)  d_in[4];
    const float* Wq_a = (const float*)d_in[5];
    const float* Wk_a = (const float*)d_in[6];
    const float* Wv_a = (const float*)d_in[7];
    const float* Wo_a = (const float*)d_in[8];
    const float* Wq_e = (const float*)d_in[9];
    const float* Wk_e = (const float*)d_in[10];
    const float* Wv_e = (const float*)d_in[11];
    const float* Wo_e = (const float*)d_in[12];
    const float* W1   = (const float*)d_in[13];
    const float* b1   = (const float*)d_in[14];
    const float* W2   = (const float*)d_in[15];
    const float* b2   = (const float*)d_in[16];
    const float* ln1g = (const float*)d_in[17];
    const float* ln1b = (const float*)d_in[18];
    const float* ln2g = (const float*)d_in[19];
    const float* ln2b = (const float*)d_in[20];
    const float* ln3g = (const float*)d_in[21];
    const float* ln3b = (const float*)d_in[22];
    const float* Wrbf = (const float*)d_in[23];
    const float* Wc   = (const float*)d_in[24];
    const float* bc   = (const float*)d_in[25];

    float* buf = nullptr;
    cudaGetSymbolAddress((void**)&buf, g_buf);
    float* h    = buf + OFF_H;
    float* qb   = buf + OFF_Q;
    float* kb   = qb + E_ * D_;
    float* vb   = qb + 2 * E_ * D_;
    float* att  = buf + OFF_ATT;
    float* mid  = buf + OFF_MID;
    float* rbf  = buf + OFF_RBF;
    float* px   = buf + OFF_PX;
    float* xb   = buf + OFF_X;
    int4*  meta = (int4*)(buf + OFF_META);
    float* rbfW = buf + OFF_RBFW;
    float* part = buf + OFF_PART;
    unsigned* whi = (unsigned*)(buf + OFF_WHI);
    unsigned* wlo = (unsigned*)(buf + OFF_WLO);

    dim3 g1(1, E_ / 32, 1);          // 96 blocks
    dim3 g3(1, E_ / 32, 3);          // 288 blocks
    dim3 gF(FF_ / 128, E_ / 32, 1);  // 384 blocks
    dim3 g2(1, E_ / 32, 2);          // 192 blocks (FF2 split-K)
    dim3 gAttn(E_ / 8, H_);          // 384 blocks
    dim3 gW(384, 11, 1);             // weight pre-split

    prep_kernel<<<(E_ + 127) / 128, 128>>>(edge_index, block_ids, node_coords,
                                           edge_coords, meta, rbf, px, xb);
    build_kernel<<<E_, 128>>>(meta);
    wsplit_kernel<<<gW, 256>>>(Wq_a, Wk_a, Wv_a, Wo_a, Wq_e, Wk_e, Wv_e, Wo_e,
                               W1, W2, Wrbf, whi, wlo);

    // rbfW_l = rbf @ Wrbf[l]; z=0 -> h = edge_features + rbfW_0; z=1,2 -> rbfW
    mma_gemm<5><<<g3, 256>>>(rbf, whi, wlo, WRBF(0), WRBF(1), WRBF(2),
                             h, rbfW, edge_features, E_, R_, R_, 0, D_,
                             nullptr, nullptr, nullptr);

    for (int l = 0; l < L_; l++) {
        const float* nextRbfW = (l < 2) ? (rbfW + (size_t)l * E_ * D_) : nullptr;

        // --- intra attention ---
        mma_gemm<0><<<g3, 256>>>(h, whi, wlo, WQKV(0, l), WQKV(1, l), WQKV(2, l),
                                 qb, nullptr, nullptr, E_, D_, D_, 0, D_,
                                 nullptr, nullptr, nullptr);
        attn_kernel<true><<<gAttn, 256>>>(qb, kb, vb, xb, att, px);
        mma_gemm<3><<<g1, 256>>>(att, whi, wlo, WQKV(3, l), 0, 0,
                                 h, nullptr, h, E_, D_, D_, 0, D_,
                                 nullptr, ln1g + l * D_, ln1b + l * D_);

        // --- inter attention ---
        mma_gemm<0><<<g3, 256>>>(h, whi, wlo, WQKV(4, l), WQKV(5, l), WQKV(6, l),
                                 qb, nullptr, nullptr, E_, D_, D_, 0, D_,
                                 nullptr, nullptr, nullptr);
        attn_kernel<false><<<gAttn, 256>>>(qb, kb, vb, xb, att, nullptr);
        mma_gemm<3><<<g1, 256>>>(att, whi, wlo, WQKV(7, l), 0, 0,
                                 h, nullptr, h, E_, D_, D_, 0, D_,
                                 nullptr, ln2g + l * D_, ln2b + l * D_);

        // --- FFN: up-proj (silu), split-K down-proj, fused epilogue ---
        mma_gemm<2><<<gF, 256>>>(h, whi, wlo, WW1(l), 0, 0,
                                 mid, nullptr, nullptr, E_, D_, D_, 0, FF_,
                                 b1 + l * FF_, nullptr, nullptr);
        mma_gemm<0><<<g2, 256>>>(mid, whi, wlo, WW2(l, 0), WW2(l, 1), 0,
                                 part, nullptr, nullptr, E_, 256, FF_, 256, D_,
                                 nullptr, nullptr, nullptr);
        ff2_epi_kernel<<<E_, 128>>>(part, h, b2 + l * D_,
                                    ln3g + l * D_, ln3b + l * D_,
                                    Wc + l * D_, bc + l, px, xb, nextRbfW);
    }

    out_kernel<<<(out_size + 255) / 256, 256>>>(h, xb, (float*)d_out, out_size);
}